// round 7
// baseline (speedup 1.0000x reference)
#include <cuda_runtime.h>
#include <math.h>

#define GRID_N   16
#define IN_DIM   64
#define OUT_DIM  64
#define BATCH    1024
#define NCOEF    19

#define BT 32                 // batch tile (warp lanes = b)
#define OB 4                  // o-columns per block
#define THREADS 256

// SMEM float offsets: S4 (2048 float4 = 8192 floats, also staging bounce),
// cst (4864 floats, [i][m][o]), xs (BT*65).
#define S4_F      8192
#define CST_F     (OB * IN_DIM * NCOEF)          // 4864
#define XS_F      (BT * 65)                      // 2080
#define SMEM_BYTES ((S4_F + CST_F + XS_F) * 4)   // 60544

__device__ __forceinline__ int swz(int i) {      // output-transpose swizzle
    return ((i & 31) ^ (i >> 2)) & 31;
}

__global__ __launch_bounds__(THREADS)
void kan_kernel(const float* __restrict__ x,
                const float* __restrict__ coef,
                const float* __restrict__ grid,
                float* __restrict__ out) {
    extern __shared__ float sm[];
    float4* S4     = (float4*)sm;                // results [i][b^swz] (32 KB)
    float*  bounce = sm;                         // staging alias (first 19456 B)
    float*  cst    = sm + S4_F;                  // coef [i][m][o]
    float*  xs     = sm + S4_F + CST_F;          // x tile [b][i] pitch 65

    const int b0 = (blockIdx.x & 31) * BT;
    const int o0 = (blockIdx.x >> 5) * OB;
    const int lane = threadIdx.x & 31;
    const int warp = threadIdx.x >> 5;

    // ---- Stage raw coef tile (coalesced float4) into bounce + x tile.
    {
        const float4* src = (const float4*)(coef + (size_t)o0 * IN_DIM * NCOEF);
        #pragma unroll
        for (int t = threadIdx.x; t < CST_F / 4; t += THREADS)
            ((float4*)bounce)[t] = src[t];
        #pragma unroll
        for (int t = threadIdx.x; t < BT * IN_DIM; t += THREADS) {
            int bb = t >> 6, i = t & 63;
            xs[bb * 65 + i] = x[(b0 + bb) * IN_DIM + i];
        }
    }
    const float g3    = grid[3];
    const float inv_h = 1.0f / (grid[4] - g3);
    const float k6    = 1.0f / 6.0f;
    __syncthreads();

    // ---- Build cst[i][m][o]: thread = one (o,i) row; row base = 19*tid in bounce.
    {
        int o = threadIdx.x >> 6, i = threadIdx.x & 63;
        const float* rowp = bounce + threadIdx.x * NCOEF;   // stride 19: conflict-free LDS
        #pragma unroll
        for (int m = 0; m < NCOEF; m++)
            cst[i * (NCOEF * OB) + m * OB + o] = rowp[m];
    }
    __syncthreads();

    // ---- Compute: 8 i's per thread; one LDS.128 per tap feeds 4 o-outputs.
    #pragma unroll
    for (int ii = 0; ii < 8; ii++) {
        const int i = warp * 8 + ii;
        const float xv = xs[lane * 65 + i];
        float t = (xv - g3) * inv_h;
        int i0 = (int)floorf(t);
        i0 = min(GRID_N - 1, max(0, i0));
        const float u  = t - (float)i0;
        const float om = 1.0f - u;
        const float u2 = u * u;
        const float w0 = om * om * om * k6;
        const float w3 = u2 * u * k6;
        const float w1 = fmaf(u2, fmaf(0.5f, u, -1.0f), 2.0f / 3.0f);
        const float w2 = 1.0f - w0 - w1 - w3;

        // 16-slot window per instruction -> 2-phase, conflict-free LDS.128.
        const float4* c = (const float4*)cst + i * NCOEF + i0;
        float4 c0 = c[0], c1 = c[1], c2 = c[2], c3 = c[3];
        float4 r;
        r.x = fmaf(w3, c3.x, fmaf(w2, c2.x, fmaf(w1, c1.x, w0 * c0.x)));
        r.y = fmaf(w3, c3.y, fmaf(w2, c2.y, fmaf(w1, c1.y, w0 * c0.y)));
        r.z = fmaf(w3, c3.z, fmaf(w2, c2.z, fmaf(w1, c1.z, w0 * c0.z)));
        r.w = fmaf(w3, c3.w, fmaf(w2, c2.w, fmaf(w1, c1.w, w0 * c0.w)));
        S4[i * BT + (lane ^ swz(i))] = r;   // perfect 4-phase STS.128
    }
    __syncthreads();

    // ---- Store: assemble float4-over-i from float4-over-o slots (degree-2 LDS).
    #pragma unroll
    for (int k = 0; k < 8; k++) {
        int t  = threadIdx.x + k * THREADS;
        int i4 = t & 15;
        int o  = (t >> 4) & 3;
        int bb = t >> 6;
        float v0, v1, v2, v3;
        {
            int i;
            i = i4 * 4 + 0; v0 = ((const float*)(S4 + i * BT + (bb ^ swz(i))))[o];
            i = i4 * 4 + 1; v1 = ((const float*)(S4 + i * BT + (bb ^ swz(i))))[o];
            i = i4 * 4 + 2; v2 = ((const float*)(S4 + i * BT + (bb ^ swz(i))))[o];
            i = i4 * 4 + 3; v3 = ((const float*)(S4 + i * BT + (bb ^ swz(i))))[o];
        }
        reinterpret_cast<float4*>(out)[((size_t)(b0 + bb) * OUT_DIM + (o0 + o)) * (IN_DIM / 4) + i4] =
            make_float4(v0, v1, v2, v3);
    }
}

extern "C" void kernel_launch(void* const* d_in, const int* in_sizes, int n_in,
                              void* d_out, int out_size) {
    const float* x    = (const float*)d_in[0];
    const float* coef = (const float*)d_in[1];
    const float* grid = (const float*)d_in[2];
    float* out        = (float*)d_out;

    cudaFuncSetAttribute(kan_kernel, cudaFuncAttributeMaxDynamicSharedMemorySize,
                         SMEM_BYTES);
    kan_kernel<<<(BATCH / BT) * (OUT_DIM / OB), THREADS, SMEM_BYTES>>>(x, coef, grid, out);
}